// round 7
// baseline (speedup 1.0000x reference)
#include <cuda_runtime.h>
#include <math.h>

#define B_  32
#define L_  4096
#define D_  1024
#define D4_ (D_ / 4)           // 256 float4 per row
#define NA_ 8
#define NCHUNK 16
#define LCHUNK (L_ / NCHUNK)   // 256
#define NW_ 8                  // warps per accum block

// Partial sums per (b, l-chunk, action, d). 16.8 MB scratch.
__device__ float g_part[B_ * NCHUNK * NA_ * D_];
// Per (b, l-chunk, action) masked counts.
__device__ int   g_cnt [B_ * NCHUNK * NA_];

// ---------------------------------------------------------------------------
// Kernel 1: masked segmented sum into per-chunk partials.
// grid = (NCHUNK, B), 256 threads; thread owns one float4 column (d4 = tid).
// Rows are stably partitioned by action with warp ballots, then the main loop
// is branchless (one accumulator per group) with 4 loads in flight.
// (Measured ~85-88 us, near HBM floor — keep unchanged.)
// ---------------------------------------------------------------------------
__global__ __launch_bounds__(256, 6)
void accum_kernel(const float4* __restrict__ emb4,
                  const int* __restrict__ actions,
                  const int* __restrict__ mask)
{
    const int chunk = blockIdx.x;
    const int b     = blockIdx.y;
    const int tid   = threadIdx.x;
    const int l0    = chunk * LCHUNK;
    const int w     = tid >> 5, lane = tid & 31;

    __shared__ short s_order[LCHUNK];
    __shared__ int   s_wcnt[NA_ * NW_];
    __shared__ int   s_woff[NA_ * NW_ + 1];

    // mask is bool upcast to a 4-byte type by the harness; nonzero = True.
    int act;
    {
        int a = actions[b * L_ + l0 + tid];
        int m = mask[b * L_ + l0 + tid];
        act = (m != 0) ? a : -1;
    }

    // Stable partition by action: warp ballots + popc ranks.
    const unsigned lt = (1u << lane) - 1u;
    int myrank = 0;
    #pragma unroll
    for (int aa = 0; aa < NA_; ++aa) {
        unsigned bal = __ballot_sync(0xffffffffu, act == aa);
        if (lane == 0) s_wcnt[aa * NW_ + w] = __popc(bal);
        if (act == aa) myrank = __popc(bal & lt);
    }
    __syncthreads();
    if (tid == 0) {
        int acc = 0;
        #pragma unroll
        for (int q = 0; q < NA_ * NW_; ++q) { s_woff[q] = acc; acc += s_wcnt[q]; }
        s_woff[NA_ * NW_] = acc;
    }
    __syncthreads();
    if (act >= 0) s_order[s_woff[act * NW_ + w] + myrank] = (short)tid;
    if (tid < NA_)
        g_cnt[(b * NCHUNK + chunk) * NA_ + tid] =
            s_woff[(tid + 1) * NW_] - s_woff[tid * NW_];
    __syncthreads();

    const float4* base = emb4 + ((size_t)b * L_ + l0) * D4_ + tid;
    float4* outp = reinterpret_cast<float4*>(g_part)
                   + (size_t)(b * NCHUNK + chunk) * NA_ * D4_ + tid;

    #pragma unroll 1
    for (int a = 0; a < NA_; ++a) {
        float4 acc = make_float4(0.f, 0.f, 0.f, 0.f);
        const int s = s_woff[a * NW_], e = s_woff[(a + 1) * NW_];
        int i = s;
        for (; i + 4 <= e; i += 4) {
            const float4 v0 = base[(int)s_order[i]     * D4_];
            const float4 v1 = base[(int)s_order[i + 1] * D4_];
            const float4 v2 = base[(int)s_order[i + 2] * D4_];
            const float4 v3 = base[(int)s_order[i + 3] * D4_];
            acc.x += (v0.x + v1.x) + (v2.x + v3.x);
            acc.y += (v0.y + v1.y) + (v2.y + v3.y);
            acc.z += (v0.z + v1.z) + (v2.z + v3.z);
            acc.w += (v0.w + v1.w) + (v2.w + v3.w);
        }
        for (; i < e; ++i) {
            const float4 v = base[(int)s_order[i] * D4_];
            acc.x += v.x; acc.y += v.y; acc.z += v.z; acc.w += v.w;
        }
        outp[a * D4_] = acc;
    }
}

// ---------------------------------------------------------------------------
// Kernel 2: head. grid = (NA, B/2) = 128 blocks (single wave on 148 SMs),
// 512 threads. Each block handles one action and TWO batches, sharing every
// weight load between the two batch accumulators.
// ---------------------------------------------------------------------------
__global__ __launch_bounds__(512)
void head_kernel(const float* __restrict__ sw1, const float* __restrict__ sb1,
                 const float* __restrict__ sw2, const float* __restrict__ sb2,
                 const float* __restrict__ ew1, const float* __restrict__ eb1,
                 const float* __restrict__ ew2, const float* __restrict__ eb2,
                 float* __restrict__ out)
{
    const int a   = blockIdx.x;
    const int b0  = blockIdx.y * 2;        // handles b0 and b0+1
    const int tid = threadIdx.x;

    __shared__ float s_feat[2][D_];
    __shared__ float s_part[2][512];
    __shared__ float s_h1[2][128];
    __shared__ float s_eh[2][64];
    __shared__ float s_logit[2][14];
    __shared__ float s_eff[2][3];
    __shared__ float s_inv[2], s_seen[2];

    // ---- counts ----
    if (tid < 2) {
        int c = 0;
        #pragma unroll
        for (int ch = 0; ch < NCHUNK; ++ch)
            c += g_cnt[((b0 + tid) * NCHUNK + ch) * NA_ + a];
        s_inv[tid]  = 1.0f / fmaxf((float)c, 1.0f);
        s_seen[tid] = (c > 0) ? 1.0f : 0.0f;
    }

    // ---- feats: 2 batches x 1024 d = 2048 columns, 4 per thread ----
    float f[4];
    #pragma unroll
    for (int k = 0; k < 4; ++k) {
        const int col = tid + k * 512;           // col = bb*1024 + d
        const int bb  = col >> 10, d = col & 1023;
        const float* gp = g_part + ((size_t)(b0 + bb) * NCHUNK * NA_ + a) * D_ + d;
        float s = 0.f;
        #pragma unroll
        for (int ch = 0; ch < NCHUNK; ++ch)
            s += gp[(size_t)ch * NA_ * D_];
        f[k] = s;
    }
    __syncthreads();            // s_inv ready
    #pragma unroll
    for (int k = 0; k < 4; ++k) {
        const int col = tid + k * 512;
        const int bb  = col >> 10, d = col & 1023;
        s_feat[bb][d] = f[k] * s_inv[bb];
    }
    __syncthreads();

    // ---- MLP1 layer 1: 128 neurons, 4 d-groups; dual chains x 2 batches ----
    {
        const int n = tid & 127, g = tid >> 7;   // g in 0..3
        float a0A = 0.f, a0B = 0.f, a1A = 0.f, a1B = 0.f;
        #pragma unroll 4
        for (int i = 0; i < 256; i += 2) {
            const int d = g * 256 + i;
            const float w0 = sw1[d * 128 + n];
            const float w1 = sw1[(d + 1) * 128 + n];
            a0A = fmaf(s_feat[0][d],     w0, a0A);
            a0B = fmaf(s_feat[0][d + 1], w1, a0B);
            a1A = fmaf(s_feat[1][d],     w0, a1A);
            a1B = fmaf(s_feat[1][d + 1], w1, a1B);
        }
        s_part[0][tid] = a0A + a0B;
        s_part[1][tid] = a1A + a1B;
    }
    __syncthreads();
    if (tid < 256) {
        const int bb = tid >> 7, n = tid & 127;
        float v = (s_part[bb][n] + s_part[bb][128 + n])
                + (s_part[bb][256 + n] + s_part[bb][384 + n]);
        s_h1[bb][n] = fmaxf(v + sb1[n], 0.0f);
    }
    __syncthreads();

    // ---- effect MLP layer 1: 64 neurons, 8 d-groups; dual chains x 2 b ----
    {
        const int n = tid & 63, g = tid >> 6;    // g in 0..7
        float a0A = 0.f, a0B = 0.f, a1A = 0.f, a1B = 0.f;
        #pragma unroll 4
        for (int i = 0; i < 128; i += 2) {
            const int d = g * 128 + i;
            const float w0 = ew1[d * 64 + n];
            const float w1 = ew1[(d + 1) * 64 + n];
            a0A = fmaf(s_feat[0][d],     w0, a0A);
            a0B = fmaf(s_feat[0][d + 1], w1, a0B);
            a1A = fmaf(s_feat[1][d],     w0, a1A);
            a1B = fmaf(s_feat[1][d + 1], w1, a1B);
        }
        s_part[0][tid] = a0A + a0B;
        s_part[1][tid] = a1A + a1B;
    }
    __syncthreads();
    if (tid < 128) {
        const int bb = tid >> 6, n = tid & 63;
        float v = 0.f;
        #pragma unroll
        for (int g = 0; g < 8; ++g) v += s_part[bb][g * 64 + n];
        s_eh[bb][n] = fmaxf(v + eb1[n], 0.0f);
    }
    __syncthreads();

    // ---- layer 2: warp-per-output, both batches per warp ----
    {
        const int w = tid >> 5, lane = tid & 31;
        if (w < 14) {
            float acc0 = 0.f, acc1 = 0.f;
            #pragma unroll
            for (int k = lane; k < 128; k += 32) {
                const float wv = sw2[k * 14 + w];
                acc0 = fmaf(s_h1[0][k], wv, acc0);
                acc1 = fmaf(s_h1[1][k], wv, acc1);
            }
            #pragma unroll
            for (int off = 16; off > 0; off >>= 1) {
                acc0 += __shfl_down_sync(0xffffffffu, acc0, off);
                acc1 += __shfl_down_sync(0xffffffffu, acc1, off);
            }
            if (lane == 0) {
                s_logit[0][w] = acc0 + sb2[w];
                s_logit[1][w] = acc1 + sb2[w];
            }
        } else if (w < 16) {
            const int bb = w - 14;
            #pragma unroll
            for (int j = 0; j < 3; ++j) {
                float acc = fmaf(s_eh[bb][lane], ew2[lane * 3 + j],
                                 s_eh[bb][lane + 32] * ew2[(lane + 32) * 3 + j]);
                #pragma unroll
                for (int off = 16; off > 0; off >>= 1)
                    acc += __shfl_down_sync(0xffffffffu, acc, off);
                if (lane == 0) s_eff[bb][j] = acc + eb2[j];
            }
        }
    }
    __syncthreads();

    // Output layout (flat float32, reference tuple order):
    //   [0,512)     shift (B,8,2)   [512,2304)  dx_logits (B,8,7)
    //   [2304,4096) dy_logits       [4096,4352) sig(e0)*seen
    //   [4352,4608) sig(e1)*seen    [4608,4864) e2*seen
    if (tid < 28) {
        const int bb = tid / 14, o = tid % 14;
        const int ba = (b0 + bb) * NA_ + a;
        if (o < 7) out[512  + ba * 7 + o]       = s_logit[bb][o];
        else       out[2304 + ba * 7 + (o - 7)] = s_logit[bb][o];
    }

    if (tid < 2) {
        const int bb = tid;
        const int ba = (b0 + bb) * NA_ + a;
        const float seen = s_seen[bb];
        const float bins[7] = {-16.f, -8.f, -4.f, 0.f, 4.f, 8.f, 16.f};
        #pragma unroll
        for (int h = 0; h < 2; ++h) {
            const float* lg = &s_logit[bb][h * 7];
            float mx = lg[0];
            #pragma unroll
            for (int j = 1; j < 7; ++j) mx = fmaxf(mx, lg[j]);
            float den = 0.f, num = 0.f;
            #pragma unroll
            for (int j = 0; j < 7; ++j) {
                const float e = __expf(lg[j] - mx);
                den += e;
                num += e * bins[j];
            }
            out[ba * 2 + h] = (num / den) * seen;
        }
        out[4096 + ba] = (1.0f / (1.0f + __expf(-s_eff[bb][0]))) * seen;
        out[4352 + ba] = (1.0f / (1.0f + __expf(-s_eff[bb][1]))) * seen;
        out[4608 + ba] = s_eff[bb][2] * seen;
    }
}

// ---------------------------------------------------------------------------
extern "C" void kernel_launch(void* const* d_in, const int* in_sizes, int n_in,
                              void* d_out, int out_size)
{
    const float4* emb4 = (const float4*)d_in[0];
    const int*    act  = (const int*)d_in[1];
    const int*    mask = (const int*)d_in[2];
    const float* sw1 = (const float*)d_in[3];
    const float* sb1 = (const float*)d_in[4];
    const float* sw2 = (const float*)d_in[5];
    const float* sb2 = (const float*)d_in[6];
    const float* ew1 = (const float*)d_in[7];
    const float* eb1 = (const float*)d_in[8];
    const float* ew2 = (const float*)d_in[9];
    const float* eb2 = (const float*)d_in[10];
    float* out = (float*)d_out;

    accum_kernel<<<dim3(NCHUNK, B_), 256>>>(emb4, act, mask);
    head_kernel<<<dim3(NA_, B_ / 2), 512>>>(sw1, sb1, sw2, sb2,
                                            ew1, eb1, ew2, eb2, out);
}

// round 8
// speedup vs baseline: 1.2439x; 1.2439x over previous
#include <cuda_runtime.h>
#include <math.h>

#define B_  32
#define L_  4096
#define D_  1024
#define D4_ (D_ / 4)           // 256 float4 per row
#define NA_ 8
#define NCHUNK 16
#define LCHUNK (L_ / NCHUNK)   // 256
#define NW_ 8                  // warps per accum block

// Partial sums per (b, l-chunk, action, d). 16.8 MB scratch.
__device__ float g_part[B_ * NCHUNK * NA_ * D_];
// Per (b, l-chunk, action) masked counts.
__device__ int   g_cnt [B_ * NCHUNK * NA_];

// ---------------------------------------------------------------------------
// Kernel 1: masked segmented sum into per-chunk partials.
// grid = (NCHUNK, B), 256 threads; thread owns one float4 column (d4 = tid).
// Rows are stably partitioned by action with warp ballots, then the main loop
// is branchless (one accumulator per group) with 4 loads in flight.
// (Measured ~85-88 us, near HBM floor — unchanged.)
// ---------------------------------------------------------------------------
__global__ __launch_bounds__(256, 6)
void accum_kernel(const float4* __restrict__ emb4,
                  const int* __restrict__ actions,
                  const int* __restrict__ mask)
{
    const int chunk = blockIdx.x;
    const int b     = blockIdx.y;
    const int tid   = threadIdx.x;
    const int l0    = chunk * LCHUNK;
    const int w     = tid >> 5, lane = tid & 31;

    __shared__ short s_order[LCHUNK];
    __shared__ int   s_wcnt[NA_ * NW_];
    __shared__ int   s_woff[NA_ * NW_ + 1];

    // mask is bool upcast to a 4-byte type by the harness; nonzero = True.
    int act;
    {
        int a = actions[b * L_ + l0 + tid];
        int m = mask[b * L_ + l0 + tid];
        act = (m != 0) ? a : -1;
    }

    // Stable partition by action: warp ballots + popc ranks.
    const unsigned lt = (1u << lane) - 1u;
    int myrank = 0;
    #pragma unroll
    for (int aa = 0; aa < NA_; ++aa) {
        unsigned bal = __ballot_sync(0xffffffffu, act == aa);
        if (lane == 0) s_wcnt[aa * NW_ + w] = __popc(bal);
        if (act == aa) myrank = __popc(bal & lt);
    }
    __syncthreads();
    if (tid == 0) {
        int acc = 0;
        #pragma unroll
        for (int q = 0; q < NA_ * NW_; ++q) { s_woff[q] = acc; acc += s_wcnt[q]; }
        s_woff[NA_ * NW_] = acc;
    }
    __syncthreads();
    if (act >= 0) s_order[s_woff[act * NW_ + w] + myrank] = (short)tid;
    if (tid < NA_)
        g_cnt[(b * NCHUNK + chunk) * NA_ + tid] =
            s_woff[(tid + 1) * NW_] - s_woff[tid * NW_];
    __syncthreads();

    const float4* base = emb4 + ((size_t)b * L_ + l0) * D4_ + tid;
    float4* outp = reinterpret_cast<float4*>(g_part)
                   + (size_t)(b * NCHUNK + chunk) * NA_ * D4_ + tid;

    #pragma unroll 1
    for (int a = 0; a < NA_; ++a) {
        float4 acc = make_float4(0.f, 0.f, 0.f, 0.f);
        const int s = s_woff[a * NW_], e = s_woff[(a + 1) * NW_];
        int i = s;
        for (; i + 4 <= e; i += 4) {
            const float4 v0 = base[(int)s_order[i]     * D4_];
            const float4 v1 = base[(int)s_order[i + 1] * D4_];
            const float4 v2 = base[(int)s_order[i + 2] * D4_];
            const float4 v3 = base[(int)s_order[i + 3] * D4_];
            acc.x += (v0.x + v1.x) + (v2.x + v3.x);
            acc.y += (v0.y + v1.y) + (v2.y + v3.y);
            acc.z += (v0.z + v1.z) + (v2.z + v3.z);
            acc.w += (v0.w + v1.w) + (v2.w + v3.w);
        }
        for (; i < e; ++i) {
            const float4 v = base[(int)s_order[i] * D4_];
            acc.x += v.x; acc.y += v.y; acc.z += v.z; acc.w += v.w;
        }
        outp[a * D4_] = acc;
    }
}

// ---------------------------------------------------------------------------
// Kernel 2: head. grid = (NA, B) = 256 blocks, 1024 threads — maximize
// concurrent load chains (the head is L2-latency-bound; traffic irrelevant).
// ---------------------------------------------------------------------------
__global__ __launch_bounds__(1024)
void head_kernel(const float* __restrict__ sw1, const float* __restrict__ sb1,
                 const float* __restrict__ sw2, const float* __restrict__ sb2,
                 const float* __restrict__ ew1, const float* __restrict__ eb1,
                 const float* __restrict__ ew2, const float* __restrict__ eb2,
                 float* __restrict__ out)
{
    const int a   = blockIdx.x;
    const int b   = blockIdx.y;
    const int tid = threadIdx.x;

    __shared__ float s_feat[D_];
    __shared__ float s_part[1024];
    __shared__ float s_h1[128];
    __shared__ float s_eh[64];
    __shared__ float s_logit[14];
    __shared__ float s_eff[3];
    __shared__ float s_scal[2];   // [0] = inv_cnt, [1] = seen

    // ---- counts (from g_cnt) ----
    if (tid == 0) {
        int c = 0;
        #pragma unroll
        for (int ch = 0; ch < NCHUNK; ++ch)
            c += g_cnt[(b * NCHUNK + ch) * NA_ + a];
        s_scal[0] = 1.0f / fmaxf((float)c, 1.0f);
        s_scal[1] = (c > 0) ? 1.0f : 0.0f;
    }

    // ---- feats: one d-column per thread over 16 chunk partials ----
    float f0 = 0.f;
    const float* gp = g_part + ((size_t)b * NCHUNK * NA_ + a) * D_;
    #pragma unroll
    for (int ch = 0; ch < NCHUNK; ++ch)
        f0 += gp[(size_t)ch * NA_ * D_ + tid];
    __syncthreads();           // s_scal ready
    const float inv_cnt = s_scal[0];
    const float seen    = s_scal[1];
    s_feat[tid] = f0 * inv_cnt;
    __syncthreads();

    // ---- MLP1 layer 1: 128 neurons, 8 threads each; dual acc chains ----
    {
        const int n = tid & 127, g = tid >> 7;      // g in 0..7
        float accA = 0.f, accB = 0.f;
        #pragma unroll 4
        for (int i = 0; i < 128; i += 2) {
            const int d = g * 128 + i;
            accA = fmaf(s_feat[d],     sw1[d * 128 + n],       accA);
            accB = fmaf(s_feat[d + 1], sw1[(d + 1) * 128 + n], accB);
        }
        s_part[tid] = accA + accB;
    }
    __syncthreads();
    if (tid < 128) {
        float v = ((s_part[tid]       + s_part[128 + tid])
                 + (s_part[256 + tid] + s_part[384 + tid]))
                + ((s_part[512 + tid] + s_part[640 + tid])
                 + (s_part[768 + tid] + s_part[896 + tid]));
        s_h1[tid] = fmaxf(v + sb1[tid], 0.0f);
    }
    __syncthreads();

    // ---- effect MLP layer 1: 64 neurons, 16 threads each; dual chains ----
    {
        const int n = tid & 63, g = tid >> 6;       // g in 0..15
        float accA = 0.f, accB = 0.f;
        #pragma unroll 4
        for (int i = 0; i < 64; i += 2) {
            const int d = g * 64 + i;
            accA = fmaf(s_feat[d],     ew1[d * 64 + n],       accA);
            accB = fmaf(s_feat[d + 1], ew1[(d + 1) * 64 + n], accB);
        }
        s_part[tid] = accA + accB;
    }
    __syncthreads();
    if (tid < 64) {
        float v = 0.f;
        #pragma unroll
        for (int g = 0; g < 16; ++g) v += s_part[g * 64 + tid];
        s_eh[tid] = fmaxf(v + eb1[tid], 0.0f);
    }
    __syncthreads();

    // ---- layer 2: warp-per-output ----
    {
        const int w = tid >> 5, lane = tid & 31;
        if (w < 14) {
            float acc = 0.f;
            #pragma unroll
            for (int k = lane; k < 128; k += 32)
                acc = fmaf(s_h1[k], sw2[k * 14 + w], acc);
            #pragma unroll
            for (int off = 16; off > 0; off >>= 1)
                acc += __shfl_down_sync(0xffffffffu, acc, off);
            if (lane == 0) s_logit[w] = acc + sb2[w];
        } else if (w == 14) {
            #pragma unroll
            for (int j = 0; j < 3; ++j) {
                float acc = fmaf(s_eh[lane], ew2[lane * 3 + j],
                                 s_eh[lane + 32] * ew2[(lane + 32) * 3 + j]);
                #pragma unroll
                for (int off = 16; off > 0; off >>= 1)
                    acc += __shfl_down_sync(0xffffffffu, acc, off);
                if (lane == 0) s_eff[j] = acc + eb2[j];
            }
        }
    }
    __syncthreads();

    // Output layout (flat float32, reference tuple order):
    //   [0,512)     shift (B,8,2)   [512,2304)  dx_logits (B,8,7)
    //   [2304,4096) dy_logits       [4096,4352) sig(e0)*seen
    //   [4352,4608) sig(e1)*seen    [4608,4864) e2*seen
    const int ba = b * NA_ + a;

    if (tid < 7)              out[512  + ba * 7 + tid]       = s_logit[tid];
    if (tid >= 7 && tid < 14) out[2304 + ba * 7 + (tid - 7)] = s_logit[tid];

    if (tid == 0) {
        const float bins[7] = {-16.f, -8.f, -4.f, 0.f, 4.f, 8.f, 16.f};
        #pragma unroll
        for (int h = 0; h < 2; ++h) {
            const float* lg = &s_logit[h * 7];
            float mx = lg[0];
            #pragma unroll
            for (int j = 1; j < 7; ++j) mx = fmaxf(mx, lg[j]);
            float den = 0.f, num = 0.f;
            #pragma unroll
            for (int j = 0; j < 7; ++j) {
                const float e = __expf(lg[j] - mx);
                den += e;
                num += e * bins[j];
            }
            out[ba * 2 + h] = (num / den) * seen;
        }
        out[4096 + ba] = (1.0f / (1.0f + __expf(-s_eff[0]))) * seen;
        out[4352 + ba] = (1.0f / (1.0f + __expf(-s_eff[1]))) * seen;
        out[4608 + ba] = s_eff[2] * seen;
    }
}

// ---------------------------------------------------------------------------
extern "C" void kernel_launch(void* const* d_in, const int* in_sizes, int n_in,
                              void* d_out, int out_size)
{
    const float4* emb4 = (const float4*)d_in[0];
    const int*    act  = (const int*)d_in[1];
    const int*    mask = (const int*)d_in[2];
    const float* sw1 = (const float*)d_in[3];
    const float* sb1 = (const float*)d_in[4];
    const float* sw2 = (const float*)d_in[5];
    const float* sb2 = (const float*)d_in[6];
    const float* ew1 = (const float*)d_in[7];
    const float* eb1 = (const float*)d_in[8];
    const float* ew2 = (const float*)d_in[9];
    const float* eb2 = (const float*)d_in[10];
    float* out = (float*)d_out;

    accum_kernel<<<dim3(NCHUNK, B_), 256>>>(emb4, act, mask);
    head_kernel<<<dim3(NA_, B_), 1024>>>(sw1, sb1, sw2, sb2,
                                         ew1, eb1, ew2, eb2, out);
}